// round 2
// baseline (speedup 1.0000x reference)
#include <cuda_runtime.h>
#include <cuda_bf16.h>
#include <cstdint>

// ---------------- problem constants ----------------
#define BB   32
#define CC   128
#define HH   64
#define WW   64
#define DD   256
#define FF_  512
#define HWN  4096          // H*W = 4096 = patch cols per batch too
#define EPS  1e-5f

// ---------------- static scratch ----------------
__device__ float g_y [ (size_t)BB * CC  * HWN ];   // 64 MB  dwconv out
__device__ float g_p [ (size_t)BB * DD  * HWN ];   // 128 MB token tensor
__device__ float g_kv[ (size_t)BB * 512 * HWN ];   // 256 MB k(0..255) v(256..511)
__device__ float g_h [ (size_t)BB * 512 * HWN ];   // 256 MB ffn hidden
__device__ float g_mean[ BB * HWN ];
__device__ float g_rstd[ BB * HWN ];
__device__ float g_ctx [ BB * 4 * DD ];
__device__ float g_s2[CC], g_b2[CC];

// ---------------- prep: fold BN2 ----------------
__global__ void prep_k(const float* __restrict__ g, const float* __restrict__ b,
                       const float* __restrict__ m, const float* __restrict__ v)
{
    int i = threadIdx.x;
    if (i < CC) {
        float s = g[i] * rsqrtf(v[i] + EPS);
        g_s2[i] = s;
        g_b2[i] = b[i] - m[i] * s;
    }
}

// ---------------- dwconv3x3 + BN1 + leaky ----------------
__global__ void __launch_bounds__(256) dwconv_k(
    const float* __restrict__ x, const float* __restrict__ w,
    const float* __restrict__ bg, const float* __restrict__ bbias,
    const float* __restrict__ bm, const float* __restrict__ bv)
{
    int b = blockIdx.z, c = blockIdx.y;
    int idx = blockIdx.x * 256 + threadIdx.x;      // 0..4095 pixel in plane
    __shared__ float ws[9];
    __shared__ float sc, sh;
    if (threadIdx.x < 9) ws[threadIdx.x] = w[c * 9 + threadIdx.x];
    if (threadIdx.x == 0) {
        float s = bg[c] * rsqrtf(bv[c] + EPS);
        sc = s; sh = bbias[c] - bm[c] * s;
    }
    __syncthreads();
    int h = idx >> 6, wq = idx & 63;
    const float* xp = x + ((size_t)b * CC + c) * HWN;
    float acc = 0.f;
#pragma unroll
    for (int dh = 0; dh < 3; dh++) {
        int hh = h + dh - 1;
        if (hh < 0 || hh >= HH) continue;
#pragma unroll
        for (int dw = 0; dw < 3; dw++) {
            int ww2 = wq + dw - 1;
            if (ww2 < 0 || ww2 >= WW) continue;
            acc = fmaf(xp[hh * 64 + ww2], ws[dh * 3 + dw], acc);
        }
    }
    float o = acc * sc + sh;
    o = (o > 0.f) ? o : 0.1f * o;
    g_y[((size_t)b * CC + c) * HWN + idx] = o;
}

// ---------------- per-column mean / rstd over D=256 ----------------
__global__ void colstats_k(const float* __restrict__ p)
{
    int b   = blockIdx.y;
    int col = blockIdx.x * 32 + threadIdx.x;
    int ty  = threadIdx.y;
    size_t base = (size_t)b * DD * HWN + col;
    float s = 0.f, s2 = 0.f;
    for (int d = ty; d < DD; d += 8) {
        float v = p[base + ((size_t)d << 12)];
        s += v; s2 = fmaf(v, v, s2);
    }
    __shared__ float sh1[8][32], sh2[8][32];
    sh1[ty][threadIdx.x] = s; sh2[ty][threadIdx.x] = s2;
    __syncthreads();
    if (ty == 0) {
        float a = 0.f, a2 = 0.f;
#pragma unroll
        for (int k = 0; k < 8; k++) { a += sh1[k][threadIdx.x]; a2 += sh2[k][threadIdx.x]; }
        float mean = a * (1.f / DD);
        float var  = a2 * (1.f / DD) - mean * mean;
        g_mean[b * HWN + col] = mean;
        g_rstd[b * HWN + col] = rsqrtf(var + EPS);
    }
}

// ---------------- fused q-GEMV + softmax + ctx ----------------
__global__ void __launch_bounds__(256) qsoftctx_k(
    const float* __restrict__ p,
    const float* __restrict__ lng, const float* __restrict__ lnb,
    const float* __restrict__ wq,  const float* __restrict__ qb)
{
    __shared__ float sprob[1024];
    __shared__ float wqs[256], gs[256], bs[256];
    __shared__ float red[256];
    int tid = threadIdx.x;
    int b = blockIdx.x >> 2, pq = blockIdx.x & 3;
    wqs[tid] = wq[tid]; gs[tid] = lng[tid]; bs[tid] = lnb[tid];
    __syncthreads();
    size_t pbase = (size_t)b * DD * HWN + pq * 1024;
    int cb = b * HWN + pq * 1024;
    float q0 = qb[0];
    float qv[4];
#pragma unroll
    for (int r = 0; r < 4; r++) {
        int n = tid + (r << 8);
        float m_ = g_mean[cb + n], rs_ = g_rstd[cb + n];
        float acc = q0;
#pragma unroll 4
        for (int k = 0; k < 256; k++) {
            float z = (p[pbase + ((size_t)k << 12) + n] - m_) * rs_ * gs[k] + bs[k];
            acc = fmaf(wqs[k], z, acc);
        }
        qv[r] = acc;
    }
    // block max
    float lm = fmaxf(fmaxf(qv[0], qv[1]), fmaxf(qv[2], qv[3]));
    red[tid] = lm; __syncthreads();
    for (int s = 128; s > 0; s >>= 1) { if (tid < s) red[tid] = fmaxf(red[tid], red[tid + s]); __syncthreads(); }
    float gm = red[0]; __syncthreads();
    float e[4]; float ls = 0.f;
#pragma unroll
    for (int r = 0; r < 4; r++) { e[r] = __expf(qv[r] - gm); ls += e[r]; }
    red[tid] = ls; __syncthreads();
    for (int s = 128; s > 0; s >>= 1) { if (tid < s) red[tid] += red[tid + s]; __syncthreads(); }
    float inv = 1.f / red[0];
#pragma unroll
    for (int r = 0; r < 4; r++) sprob[tid + (r << 8)] = e[r] * inv;
    __syncthreads();
    // ctx[d] = sum_n k[d,n] * prob[n]   (k rows are g_kv rows 0..255)
    int warp = tid >> 5, lane = tid & 31;
    for (int d = warp; d < 256; d += 8) {
        const float* kr = g_kv + ((size_t)b * 512 + d) * HWN + pq * 1024;
        float acc = 0.f;
#pragma unroll 8
        for (int n = lane; n < 1024; n += 32) acc = fmaf(kr[n], sprob[n], acc);
#pragma unroll
        for (int o = 16; o > 0; o >>= 1) acc += __shfl_down_sync(0xffffffffu, acc, o);
        if (lane == 0) g_ctx[(b << 10) + (pq << 8) + d] = acc;
    }
}

// ---------------- templated SGEMM ----------------
// Y[b, m, col] = sum_k W[m,k] * T(X[b, k, col]) ;  per-batch X stride = strideX
enum { BT_NONE = 0, BT_LN = 1, BT_RELUCTX = 2 };
enum { EP_STORE = 0, EP_LEAKY = 1, EP_RESID = 2, EP_PERM_P = 3, EP_PERM_OUT = 4 };

template<int BT, int EP>
__global__ void __launch_bounds__(256) gemm_k(
    const float* __restrict__ W, const float* __restrict__ X,
    float* __restrict__ Y, const float* __restrict__ bias,
    const float* __restrict__ lng, const float* __restrict__ lnb,
    int M, int K, long strideX)
{
    const int b    = blockIdx.z;
    const int colT = blockIdx.x * 128;
    const int rowT = blockIdx.y * 128;
    const float* Wp = W + (size_t)rowT * K;
    const float* Xp = X + (size_t)b * strideX + colT;
    const int cb   = b * HWN + colT;                       // LN stats base
    const int ctxb = (b << 10) + ((colT >> 10) << 8);      // ctx base (pq const per tile)

    __shared__ float As[8][128];
    __shared__ float Bs[8][128];
    float acc[8][8];
#pragma unroll
    for (int i = 0; i < 8; i++)
#pragma unroll
        for (int j = 0; j < 8; j++) acc[i][j] = 0.f;

    int tid  = threadIdx.x;
    int tx   = tid & 15, ty = tid >> 4;
    int aRow = tid >> 1, aK = (tid & 1) << 2;
    int bK   = tid >> 5, bCol = (tid & 31) << 2;

    for (int kt = 0; kt < K; kt += 8) {
        float4 av = *reinterpret_cast<const float4*>(Wp + (size_t)aRow * K + kt + aK);
        As[aK + 0][aRow] = av.x; As[aK + 1][aRow] = av.y;
        As[aK + 2][aRow] = av.z; As[aK + 3][aRow] = av.w;

        int kg = kt + bK;
        float4 bv = *reinterpret_cast<const float4*>(Xp + ((size_t)kg << 12) + bCol);
        if (BT == BT_LN) {
            float gk = lng[kg], bk = lnb[kg];
            int c = cb + bCol;
            bv.x = (bv.x - g_mean[c + 0]) * g_rstd[c + 0] * gk + bk;
            bv.y = (bv.y - g_mean[c + 1]) * g_rstd[c + 1] * gk + bk;
            bv.z = (bv.z - g_mean[c + 2]) * g_rstd[c + 2] * gk + bk;
            bv.w = (bv.w - g_mean[c + 3]) * g_rstd[c + 3] * gk + bk;
        } else if (BT == BT_RELUCTX) {
            float cv = g_ctx[ctxb + kg];
            bv.x = fmaxf(bv.x, 0.f) * cv; bv.y = fmaxf(bv.y, 0.f) * cv;
            bv.z = fmaxf(bv.z, 0.f) * cv; bv.w = fmaxf(bv.w, 0.f) * cv;
        }
        *reinterpret_cast<float4*>(&Bs[bK][bCol]) = bv;
        __syncthreads();

#pragma unroll
        for (int kk = 0; kk < 8; kk++) {
            float4 a0 = *reinterpret_cast<const float4*>(&As[kk][ty * 8]);
            float4 a1 = *reinterpret_cast<const float4*>(&As[kk][ty * 8 + 4]);
            float4 b0 = *reinterpret_cast<const float4*>(&Bs[kk][tx * 8]);
            float4 b1 = *reinterpret_cast<const float4*>(&Bs[kk][tx * 8 + 4]);
            float ar[8] = {a0.x, a0.y, a0.z, a0.w, a1.x, a1.y, a1.z, a1.w};
            float br[8] = {b0.x, b0.y, b0.z, b0.w, b1.x, b1.y, b1.z, b1.w};
#pragma unroll
            for (int i = 0; i < 8; i++)
#pragma unroll
                for (int j = 0; j < 8; j++) acc[i][j] = fmaf(ar[i], br[j], acc[i][j]);
        }
        __syncthreads();
    }

#pragma unroll
    for (int i = 0; i < 8; i++) {
        int m = rowT + ty * 8 + i;
        float bi = 0.f, rs_ = 0.f, rb_ = 0.f;
        if (EP == EP_PERM_OUT) { rs_ = g_s2[m]; rb_ = g_b2[m]; }
        else bi = bias[m];
#pragma unroll
        for (int j = 0; j < 8; j++) {
            int col = colT + tx * 8 + j;
            float v = acc[i][j];
            if (EP == EP_PERM_OUT) v = v * rs_ + rb_;
            else v += bi;
            if (EP == EP_LEAKY) v = (v > 0.f) ? v : 0.1f * v;
            if (EP == EP_PERM_P) {
                // spatial col -> patch col
                int h = col >> 6, w = col & 63;
                int pc = ((((h & 1) << 1) | (w & 1)) << 10) | ((h >> 1) << 5) | (w >> 1);
                Y[((size_t)b * M + m) * HWN + pc] = v;
            } else if (EP == EP_PERM_OUT) {
                // patch col -> spatial
                int pq = col >> 10, n = col & 1023;
                int h = ((n >> 5) << 1) | (pq >> 1);
                int w = ((n & 31) << 1) | (pq & 1);
                Y[((size_t)b * M + m) * HWN + h * 64 + w] = v;
            } else {
                size_t yb = ((size_t)b * M + m) * HWN + col;
                if (EP == EP_RESID) Y[yb] += v;
                else Y[yb] = v;
            }
        }
    }
}

// ---------------- host ----------------
extern "C" void kernel_launch(void* const* d_in, const int* in_sizes, int n_in,
                              void* d_out, int out_size)
{
    const float* x     = (const float*)d_in[0];
    const float* dw_w  = (const float*)d_in[1];
    const float* bn1_g = (const float*)d_in[2];
    const float* bn1_b = (const float*)d_in[3];
    const float* bn1_m = (const float*)d_in[4];
    const float* bn1_v = (const float*)d_in[5];
    const float* c1_w  = (const float*)d_in[6];
    const float* c1_b  = (const float*)d_in[7];
    const float* ln1_g = (const float*)d_in[8];
    const float* ln1_b = (const float*)d_in[9];
    const float* qkv_w = (const float*)d_in[10];
    const float* qkv_b = (const float*)d_in[11];
    const float* out_w = (const float*)d_in[12];
    const float* out_b = (const float*)d_in[13];
    const float* ln2_g = (const float*)d_in[14];
    const float* ln2_b = (const float*)d_in[15];
    const float* f1_w  = (const float*)d_in[16];
    const float* f1_b  = (const float*)d_in[17];
    const float* f2_w  = (const float*)d_in[18];
    const float* f2_b  = (const float*)d_in[19];
    const float* lnf_g = (const float*)d_in[20];
    const float* lnf_b = (const float*)d_in[21];
    const float* projw = (const float*)d_in[22];
    const float* bn2_g = (const float*)d_in[23];
    const float* bn2_b = (const float*)d_in[24];
    const float* bn2_m = (const float*)d_in[25];
    const float* bn2_v = (const float*)d_in[26];
    float* out = (float*)d_out;

    void *vp;
    cudaGetSymbolAddress(&vp, g_y);  float* yb = (float*)vp;
    cudaGetSymbolAddress(&vp, g_p);  float* p  = (float*)vp;
    cudaGetSymbolAddress(&vp, g_kv); float* kv = (float*)vp;
    cudaGetSymbolAddress(&vp, g_h);  float* hb = (float*)vp;

    prep_k<<<1, 128>>>(bn2_g, bn2_b, bn2_m, bn2_v);
    dwconv_k<<<dim3(16, CC, BB), 256>>>(x, dw_w, bn1_g, bn1_b, bn1_m, bn1_v);

    // c1: 128->256, spatial cols, patchify-permuted store into p
    gemm_k<BT_NONE, EP_PERM_P><<<dim3(32, 2, BB), 256>>>(
        c1_w, yb, p, c1_b, nullptr, nullptr, DD, CC, (long)CC * HWN);

    for (int l = 0; l < 2; l++) {
        const float* l1g = ln1_g + l * DD;
        const float* l1b = ln1_b + l * DD;
        const float* qw  = qkv_w + (size_t)l * 513 * DD;
        const float* qbi = qkv_b + l * 513;

        colstats_k<<<dim3(128, BB), dim3(32, 8)>>>(p);

        // kv = W_kv @ LN1(p)   (rows 1..512 of qkv)
        gemm_k<BT_LN, EP_STORE><<<dim3(32, 4, BB), 256>>>(
            qw + DD, p, kv, qbi + 1, l1g, l1b, 512, DD, (long)DD * HWN);

        // q + softmax + ctx
        qsoftctx_k<<<128, 256>>>(p, l1g, l1b, qw, qbi);

        // attn = out_w @ (relu(v)*ctx) + out_b ; p += attn   (v rows = kv+256*4096)
        gemm_k<BT_RELUCTX, EP_RESID><<<dim3(32, 2, BB), 256>>>(
            out_w + (size_t)l * DD * DD, kv + (size_t)DD * HWN, p,
            out_b + l * DD, nullptr, nullptr, DD, DD, (long)512 * HWN);

        colstats_k<<<dim3(128, BB), dim3(32, 8)>>>(p);

        // h = leaky(f1 @ LN2(p) + b1)
        gemm_k<BT_LN, EP_LEAKY><<<dim3(32, 4, BB), 256>>>(
            f1_w + (size_t)l * FF_ * DD, p, hb, f1_b + l * FF_,
            ln2_g + l * DD, ln2_b + l * DD, FF_, DD, (long)DD * HWN);

        // p += f2 @ h + b2
        gemm_k<BT_NONE, EP_RESID><<<dim3(32, 2, BB), 256>>>(
            f2_w + (size_t)l * DD * FF_, hb, p, f2_b + l * DD,
            nullptr, nullptr, DD, FF_, (long)FF_ * HWN);
    }

    colstats_k<<<dim3(128, BB), dim3(32, 8)>>>(p);

    // out = BN2(proj @ LNf(p)), un-patchified spatial store
    gemm_k<BT_LN, EP_PERM_OUT><<<dim3(32, 1, BB), 256>>>(
        projw, p, out, nullptr, lnf_g, lnf_b, CC, DD, (long)DD * HWN);
}